// round 2
// baseline (speedup 1.0000x reference)
#include <cuda_runtime.h>
#include <math.h>
#include <stdint.h>

#define Bn 4
#define Tn 8
#define Hn 256
#define Wn 256
#define Nn (Bn*Tn*Hn*Wn)   // 2,097,152

// params layout: 0:cc 1:ce 2:cw 3:cs 4:cn 5:cx(corner) 6:D
__device__ float  g_params[7 * Nn];
__device__ double g_logD;
__device__ double g_xQx;

__global__ void init_kernel() { g_logD = 0.0; g_xQx = 0.0; }

__device__ __forceinline__ uint64_t pack2(float lo, float hi) {
    uint64_t r; asm("mov.b64 %0, {%1,%2};" : "=l"(r) : "f"(lo), "f"(hi)); return r;
}
__device__ __forceinline__ uint64_t ffma2(uint64_t a, uint64_t b, uint64_t c) {
    uint64_t d; asm("fma.rn.f32x2 %0, %1, %2, %3;" : "=l"(d) : "l"(a), "l"(b), "l"(c)); return d;
}
__device__ __forceinline__ void unpack2(uint64_t v, float& lo, float& hi) {
    asm("mov.b64 {%0,%1}, %2;" : "=f"(lo), "=f"(hi) : "l"(v));
}

__device__ __forceinline__ float block_reduce_sum(float v) {
    __shared__ float red[8];
    #pragma unroll
    for (int o = 16; o > 0; o >>= 1) v += __shfl_down_sync(0xffffffffu, v, o);
    int lane = threadIdx.x & 31, wid = threadIdx.x >> 5;
    if (lane == 0) red[wid] = v;
    __syncthreads();
    if (wid == 0) {
        v = (lane < 8) ? red[lane] : 0.f;
        #pragma unroll
        for (int o = 4; o > 0; o >>= 1) v += __shfl_down_sync(0xffffffffu, v, o);
    }
    return v;  // valid on thread 0
}

// ---------------------------------------------------------------------------
// Conv 3x3 (8 -> 64 ch) via packed f32x2 FMA + nonlinearities + coeff store
// Block: 256 threads, 32x32 output tile. grid (8, 8, B)
// ---------------------------------------------------------------------------
__global__ __launch_bounds__(256, 2)
void conv_kernel(const float* __restrict__ x, const float* __restrict__ w) {
    __shared__ float xs[8][34][34];
    __shared__ __align__(16) float ws[72][8];   // [k = ic*9+kh*3+kw][g]

    const int tid = threadIdx.x;
    const int tx  = tid & 31;
    const int ty  = tid >> 5;
    const int b   = blockIdx.z;
    const int h0  = blockIdx.y * 32;
    const int w0  = blockIdx.x * 32;

    const float* xb = x + b * Tn * Hn * Wn;
    for (int i = tid; i < 8 * 34 * 34; i += 256) {
        int ic  = i / 1156;
        int rem = i - ic * 1156;
        int ly  = rem / 34;
        int lx  = rem - ly * 34;
        int gh  = h0 - 1 + ly;
        int gw  = w0 - 1 + lx;
        float v = 0.f;
        if ((unsigned)gh < (unsigned)Hn && (unsigned)gw < (unsigned)Wn)
            v = xb[(ic * Hn + gh) * Wn + gw];
        xs[ic][ly][lx] = v;
    }

    float local_logD = 0.f;

    for (int t = 0; t < Tn; ++t) {
        __syncthreads();
        for (int j = tid; j < 576; j += 256) {
            int k = j >> 3;
            int g = j & 7;
            ws[k][g] = w[(g * 8 + t) * 72 + k];
        }
        __syncthreads();

        // packed accumulators: acc2[r][p] holds (g=2p, g=2p+1)
        uint64_t acc2[4][4];
        const uint64_t z64 = 0;
        #pragma unroll
        for (int r = 0; r < 4; ++r)
            #pragma unroll
            for (int p = 0; p < 4; ++p) acc2[r][p] = z64;

        for (int ic = 0; ic < 8; ++ic) {
            #pragma unroll
            for (int kh = 0; kh < 3; ++kh) {
                #pragma unroll
                for (int kw = 0; kw < 3; ++kw) {
                    const int k = ic * 9 + kh * 3 + kw;
                    const uint64_t* wp = (const uint64_t*)&ws[k][0];
                    uint64_t w01 = wp[0], w23 = wp[1], w45 = wp[2], w67 = wp[3];
                    #pragma unroll
                    for (int r = 0; r < 4; ++r) {
                        float xv = xs[ic][ty * 4 + r + kh][tx + kw];
                        uint64_t xp = pack2(xv, xv);
                        acc2[r][0] = ffma2(xp, w01, acc2[r][0]);
                        acc2[r][1] = ffma2(xp, w23, acc2[r][1]);
                        acc2[r][2] = ffma2(xp, w45, acc2[r][2]);
                        acc2[r][3] = ffma2(xp, w67, acc2[r][3]);
                    }
                }
            }
        }

        const int wglob = w0 + tx;
        #pragma unroll
        for (int r = 0; r < 4; ++r) {
            int hglob = h0 + ty * 4 + r;
            int idx = ((b * Tn + t) * Hn + hglob) * Wn + wglob;

            float a0, a1, a2, a3, a4, a5, a6, a7;
            unpack2(acc2[r][0], a0, a1);
            unpack2(acc2[r][1], a2, a3);
            unpack2(acc2[r][2], a4, a5);
            unpack2(acc2[r][3], a6, a7);

            // groups: 0:kappa 1:m1 2:m2 3:Hxx 4:Hxy 5:Hyx 6:Hyy 7:tau
            float kap  = 0.99f * (1.f / (1.f + __expf(-a0))) + 0.01f;
            float kap2 = kap * kap;
            float hxx  = 0.99f * (1.f / (1.f + __expf(-a3))) + 0.01f;
            float hyy  = 0.99f * (1.f / (1.f + __expf(-a6))) + 0.01f;
            float hxys = 0.1f * (tanhf(a4) + tanhf(a5));
            float tau  = 9.9f * (1.f / (1.f + __expf(-a7))) + 0.1f;
            float Dv   = 1.f / (tau * tau);
            local_logD += -2.f * __logf(tau);

            // pre-combined stencil coefficients
            g_params[0 * Nn + idx] = kap2 + 2.f * hxx + 2.f * hyy;   // cc
            g_params[1 * Nn + idx] =  0.5f * a1 - hxx;               // ce
            g_params[2 * Nn + idx] = -0.5f * a1 - hxx;               // cw
            g_params[3 * Nn + idx] =  0.5f * a2 - hyy;               // cs
            g_params[4 * Nn + idx] = -0.5f * a2 - hyy;               // cn
            g_params[5 * Nn + idx] = -0.25f * hxys;                  // cx
            g_params[6 * Nn + idx] = Dv;
        }
    }

    __syncthreads();
    float s = block_reduce_sum(local_logD);
    if (threadIdx.x == 0) atomicAdd(&g_logD, (double)s);
}

// ---------------------------------------------------------------------------
// Fused double stencil: y = A(x) on 34x34 tile (halo 1), z = A(y) on 32x32,
// r = x + z - x_prev, accumulate sum(D r^2).
// A(u) @p = cc*C + ce*E + cw*W + cs*S + cn*N + cx*(SE-NE-SW+NW)
// ---------------------------------------------------------------------------
__global__ __launch_bounds__(256)
void fused_stencil_kernel(const float* __restrict__ x) {
    __shared__ float xs[36][36];
    __shared__ float cs[6][34][34];
    __shared__ float ys[34][34];

    const int tid = threadIdx.x;
    const int tx  = tid & 31;
    const int ty  = tid >> 5;
    const int bt  = blockIdx.z;        // b*T + t
    const int t   = bt & (Tn - 1);
    const int h0  = blockIdx.y * 32;
    const int w0  = blockIdx.x * 32;

    // x tile with halo 2
    const float* up = x + bt * Hn * Wn;
    for (int i = tid; i < 36 * 36; i += 256) {
        int ly = i / 36, lx = i - ly * 36;
        int gh = h0 - 2 + ly, gw = w0 - 2 + lx;
        xs[ly][lx] = ((unsigned)gh < (unsigned)Hn && (unsigned)gw < (unsigned)Wn)
                         ? up[gh * Wn + gw] : 0.f;
    }
    // coeff tiles with halo 1
    #pragma unroll
    for (int f = 0; f < 6; ++f) {
        const float* pp = g_params + f * Nn + bt * Hn * Wn;
        for (int i = tid; i < 34 * 34; i += 256) {
            int ly = i / 34, lx = i - ly * 34;
            int gh = h0 - 1 + ly, gw = w0 - 1 + lx;
            cs[f][ly][lx] = ((unsigned)gh < (unsigned)Hn && (unsigned)gw < (unsigned)Wn)
                                ? pp[gh * Wn + gw] : 0.f;
        }
    }
    __syncthreads();

    // y = A(x) on the 34x34 ring+interior (zero outside domain)
    for (int i = tid; i < 34 * 34; i += 256) {
        int ly = i / 34, lx = i - ly * 34;
        int gh = h0 - 1 + ly, gw = w0 - 1 + lx;
        float yv = 0.f;
        if ((unsigned)gh < (unsigned)Hn && (unsigned)gw < (unsigned)Wn) {
            // xs index of this point: [ly+1][lx+1]
            float c  = xs[ly + 1][lx + 1];
            float e  = xs[ly + 1][lx + 2];
            float wv = xs[ly + 1][lx + 0];
            float s  = xs[ly + 2][lx + 1];
            float n  = xs[ly + 0][lx + 1];
            float se = xs[ly + 2][lx + 2];
            float ne = xs[ly + 0][lx + 2];
            float sw = xs[ly + 2][lx + 0];
            float nw = xs[ly + 0][lx + 0];
            yv = cs[0][ly][lx] * c
               + cs[1][ly][lx] * e
               + cs[2][ly][lx] * wv
               + cs[3][ly][lx] * s
               + cs[4][ly][lx] * n
               + cs[5][ly][lx] * (se - ne - sw + nw);
        }
        ys[ly][lx] = yv;
    }
    __syncthreads();

    // z = A(y) on interior, residual + weighted square
    const float* Dp = g_params + 6 * Nn + bt * Hn * Wn;
    float local = 0.f;
    #pragma unroll
    for (int r = 0; r < 4; ++r) {
        int iy = ty * 4 + r;
        int gh = h0 + iy, gw = w0 + tx;
        int ly = iy + 1, lx = tx + 1;

        float c  = ys[ly][lx];
        float e  = ys[ly][lx + 1];
        float wv = ys[ly][lx - 1];
        float s  = ys[ly + 1][lx];
        float n  = ys[ly - 1][lx];
        float se = ys[ly + 1][lx + 1];
        float ne = ys[ly - 1][lx + 1];
        float sw = ys[ly + 1][lx - 1];
        float nw = ys[ly - 1][lx - 1];

        float z = cs[0][ly][lx] * c
                + cs[1][ly][lx] * e
                + cs[2][ly][lx] * wv
                + cs[3][ly][lx] * s
                + cs[4][ly][lx] * n
                + cs[5][ly][lx] * (se - ne - sw + nw);

        float xc    = xs[iy + 2][tx + 2];
        float xprev = (t > 0) ? x[((bt - 1) * Hn + gh) * Wn + gw] : 0.f;
        float rr = xc + z - xprev;
        local += Dp[gh * Wn + gw] * rr * rr;
    }

    __syncthreads();
    float ssum = block_reduce_sum(local);
    if (threadIdx.x == 0) atomicAdd(&g_xQx, (double)ssum);
}

__global__ void final_kernel(float* out) {
    out[0] = (float)(0.5 * (g_xQx - g_logD));
}

extern "C" void kernel_launch(void* const* d_in, const int* in_sizes, int n_in,
                              void* d_out, int out_size) {
    const float* x = (const float*)d_in[0];
    const float* w = (const float*)d_in[1];
    float* out = (float*)d_out;

    init_kernel<<<1, 1>>>();
    conv_kernel<<<dim3(8, 8, Bn), 256>>>(x, w);
    fused_stencil_kernel<<<dim3(8, 8, Bn * Tn), 256>>>(x);
    final_kernel<<<1, 1>>>(out);
}

// round 3
// speedup vs baseline: 1.0647x; 1.0647x over previous
#include <cuda_runtime.h>
#include <math.h>

#define Bn 4
#define Tn 8
#define Hn 256
#define Wn 256
#define Nn (Bn*Tn*Hn*Wn)   // 2,097,152

// params layout: 0:cc 1:ce 2:cw 3:cs 4:cn 5:cx(corner) 6:D
__device__ float g_params[7 * Nn];
__device__ float g_partLogD[256];    // conv blocks
__device__ float g_partXQX[2048];    // fused stencil blocks

__device__ __forceinline__ float block_reduce_sum(float v) {
    __shared__ float red[8];
    #pragma unroll
    for (int o = 16; o > 0; o >>= 1) v += __shfl_down_sync(0xffffffffu, v, o);
    int lane = threadIdx.x & 31, wid = threadIdx.x >> 5;
    if (lane == 0) red[wid] = v;
    __syncthreads();
    if (wid == 0) {
        v = (lane < 8) ? red[lane] : 0.f;
        #pragma unroll
        for (int o = 4; o > 0; o >>= 1) v += __shfl_down_sync(0xffffffffu, v, o);
    }
    return v;  // valid on thread 0
}

// ---------------------------------------------------------------------------
// Conv 3x3 (8 -> 64 ch), scalar FFMA (R1 known-good) + nonlinearities +
// pre-combined stencil coefficient store + per-block logD partial.
// Block: 256 threads, 32x32 output tile. grid (8, 8, B)
// ---------------------------------------------------------------------------
__global__ __launch_bounds__(256, 2)
void conv_kernel(const float* __restrict__ x, const float* __restrict__ w) {
    __shared__ float xs[8][34][34];
    __shared__ __align__(16) float ws[72][8];   // [k = ic*9+kh*3+kw][g]

    const int tid = threadIdx.x;
    const int tx  = tid & 31;
    const int ty  = tid >> 5;
    const int b   = blockIdx.z;
    const int h0  = blockIdx.y * 32;
    const int w0  = blockIdx.x * 32;

    const float* xb = x + b * Tn * Hn * Wn;
    for (int i = tid; i < 8 * 34 * 34; i += 256) {
        int ic  = i / 1156;
        int rem = i - ic * 1156;
        int ly  = rem / 34;
        int lx  = rem - ly * 34;
        int gh  = h0 - 1 + ly;
        int gw  = w0 - 1 + lx;
        float v = 0.f;
        if ((unsigned)gh < (unsigned)Hn && (unsigned)gw < (unsigned)Wn)
            v = xb[(ic * Hn + gh) * Wn + gw];
        xs[ic][ly][lx] = v;
    }

    float local_logD = 0.f;

    for (int t = 0; t < Tn; ++t) {
        __syncthreads();
        for (int j = tid; j < 576; j += 256) {
            int k = j >> 3;
            int g = j & 7;
            ws[k][g] = w[(g * 8 + t) * 72 + k];
        }
        __syncthreads();

        float acc[4][8];
        #pragma unroll
        for (int r = 0; r < 4; ++r)
            #pragma unroll
            for (int g = 0; g < 8; ++g) acc[r][g] = 0.f;

        for (int ic = 0; ic < 8; ++ic) {
            #pragma unroll
            for (int kh = 0; kh < 3; ++kh) {
                #pragma unroll
                for (int kw = 0; kw < 3; ++kw) {
                    const int k = ic * 9 + kh * 3 + kw;
                    float4 wa = *(const float4*)&ws[k][0];
                    float4 wb = *(const float4*)&ws[k][4];
                    float xv[4];
                    #pragma unroll
                    for (int r = 0; r < 4; ++r)
                        xv[r] = xs[ic][ty * 4 + r + kh][tx + kw];
                    #pragma unroll
                    for (int r = 0; r < 4; ++r) {
                        acc[r][0] += xv[r] * wa.x;
                        acc[r][1] += xv[r] * wa.y;
                        acc[r][2] += xv[r] * wa.z;
                        acc[r][3] += xv[r] * wa.w;
                        acc[r][4] += xv[r] * wb.x;
                        acc[r][5] += xv[r] * wb.y;
                        acc[r][6] += xv[r] * wb.z;
                        acc[r][7] += xv[r] * wb.w;
                    }
                }
            }
        }

        const int wglob = w0 + tx;
        #pragma unroll
        for (int r = 0; r < 4; ++r) {
            int hglob = h0 + ty * 4 + r;
            int idx = ((b * Tn + t) * Hn + hglob) * Wn + wglob;

            // groups: 0:kappa 1:m1 2:m2 3:Hxx 4:Hxy 5:Hyx 6:Hyy 7:tau
            float kap  = 0.99f * (1.f / (1.f + __expf(-acc[r][0]))) + 0.01f;
            float kap2 = kap * kap;
            float hxx  = 0.99f * (1.f / (1.f + __expf(-acc[r][3]))) + 0.01f;
            float hyy  = 0.99f * (1.f / (1.f + __expf(-acc[r][6]))) + 0.01f;
            float hxys = 0.1f * (tanhf(acc[r][4]) + tanhf(acc[r][5]));
            float tau  = 9.9f * (1.f / (1.f + __expf(-acc[r][7]))) + 0.1f;
            float Dv   = 1.f / (tau * tau);
            local_logD += -2.f * __logf(tau);

            g_params[0 * Nn + idx] = kap2 + 2.f * hxx + 2.f * hyy;   // cc
            g_params[1 * Nn + idx] =  0.5f * acc[r][1] - hxx;        // ce
            g_params[2 * Nn + idx] = -0.5f * acc[r][1] - hxx;        // cw
            g_params[3 * Nn + idx] =  0.5f * acc[r][2] - hyy;        // cs
            g_params[4 * Nn + idx] = -0.5f * acc[r][2] - hyy;        // cn
            g_params[5 * Nn + idx] = -0.25f * hxys;                  // cx
            g_params[6 * Nn + idx] = Dv;
        }
    }

    __syncthreads();
    float s = block_reduce_sum(local_logD);
    if (threadIdx.x == 0)
        g_partLogD[(blockIdx.z * 8 + blockIdx.y) * 8 + blockIdx.x] = s;
}

// ---------------------------------------------------------------------------
// Fused double stencil, lightweight smem (9.8KB):
//   phase1: y = A(x) on 34x34 (halo 1), coeffs read from global
//   phase2: z = A(y) on 32x32 interior, coeffs re-read (L1 hit)
//   r = x + z - x_prev; per-block partial of sum(D r^2)
// A(u)@p = cc*C + ce*E + cw*W + cs*S + cn*N + cx*(SE-NE-SW+NW), zero outside.
// ---------------------------------------------------------------------------
__global__ __launch_bounds__(256)
void fused_stencil_kernel(const float* __restrict__ x) {
    __shared__ float xs[36][36];
    __shared__ float ys[34][34];

    const int tid = threadIdx.x;
    const int tx  = tid & 31;
    const int ty  = tid >> 5;
    const int bt  = blockIdx.z;        // b*T + t
    const int t   = bt & (Tn - 1);
    const int h0  = blockIdx.y * 32;
    const int w0  = blockIdx.x * 32;
    const int base = bt * Hn * Wn;

    // x tile with halo 2
    const float* up = x + base;
    for (int i = tid; i < 36 * 36; i += 256) {
        int ly = i / 36, lx = i - ly * 36;
        int gh = h0 - 2 + ly, gw = w0 - 2 + lx;
        xs[ly][lx] = ((unsigned)gh < (unsigned)Hn && (unsigned)gw < (unsigned)Wn)
                         ? up[gh * Wn + gw] : 0.f;
    }
    __syncthreads();

    // phase 1: y = A(x) on 34x34 ring+interior
    for (int i = tid; i < 34 * 34; i += 256) {
        int ly = i / 34, lx = i - ly * 34;
        int gh = h0 - 1 + ly, gw = w0 - 1 + lx;
        float yv = 0.f;
        if ((unsigned)gh < (unsigned)Hn && (unsigned)gw < (unsigned)Wn) {
            int gidx = base + gh * Wn + gw;
            float c  = xs[ly + 1][lx + 1];
            float e  = xs[ly + 1][lx + 2];
            float wv = xs[ly + 1][lx + 0];
            float s  = xs[ly + 2][lx + 1];
            float n  = xs[ly + 0][lx + 1];
            float se = xs[ly + 2][lx + 2];
            float ne = xs[ly + 0][lx + 2];
            float sw = xs[ly + 2][lx + 0];
            float nw = xs[ly + 0][lx + 0];
            yv = g_params[0 * Nn + gidx] * c
               + g_params[1 * Nn + gidx] * e
               + g_params[2 * Nn + gidx] * wv
               + g_params[3 * Nn + gidx] * s
               + g_params[4 * Nn + gidx] * n
               + g_params[5 * Nn + gidx] * (se - ne - sw + nw);
        }
        ys[ly][lx] = yv;
    }
    __syncthreads();

    // phase 2: z = A(y) on interior; residual + weighted square
    float local = 0.f;
    #pragma unroll
    for (int r = 0; r < 4; ++r) {
        int iy = ty * 4 + r;
        int gh = h0 + iy, gw = w0 + tx;
        int gidx = base + gh * Wn + gw;
        int ly = iy + 1, lx = tx + 1;

        float c  = ys[ly][lx];
        float e  = ys[ly][lx + 1];
        float wv = ys[ly][lx - 1];
        float s  = ys[ly + 1][lx];
        float n  = ys[ly - 1][lx];
        float se = ys[ly + 1][lx + 1];
        float ne = ys[ly - 1][lx + 1];
        float sw = ys[ly + 1][lx - 1];
        float nw = ys[ly - 1][lx - 1];

        float z = g_params[0 * Nn + gidx] * c
                + g_params[1 * Nn + gidx] * e
                + g_params[2 * Nn + gidx] * wv
                + g_params[3 * Nn + gidx] * s
                + g_params[4 * Nn + gidx] * n
                + g_params[5 * Nn + gidx] * (se - ne - sw + nw);

        float xc    = xs[iy + 2][tx + 2];
        float xprev = (t > 0) ? x[gidx - Hn * Wn] : 0.f;
        float rr = xc + z - xprev;
        local += g_params[6 * Nn + gidx] * rr * rr;
    }

    __syncthreads();
    float ssum = block_reduce_sum(local);
    if (threadIdx.x == 0)
        g_partXQX[(blockIdx.z * 8 + blockIdx.y) * 8 + blockIdx.x] = ssum;
}

// ---------------------------------------------------------------------------
// Final reduce of partials (double accumulation), writes the scalar output.
// ---------------------------------------------------------------------------
__global__ void final_kernel(float* out) {
    __shared__ double redq[32];
    __shared__ double redl[32];
    const int tid = threadIdx.x;   // 1024 threads
    double xq = (double)g_partXQX[tid] + (double)g_partXQX[tid + 1024];
    double ld = (tid < 256) ? (double)g_partLogD[tid] : 0.0;

    #pragma unroll
    for (int o = 16; o > 0; o >>= 1) {
        xq += __shfl_down_sync(0xffffffffu, xq, o);
        ld += __shfl_down_sync(0xffffffffu, ld, o);
    }
    int lane = tid & 31, wid = tid >> 5;
    if (lane == 0) { redq[wid] = xq; redl[wid] = ld; }
    __syncthreads();
    if (wid == 0) {
        xq = redq[lane];
        ld = redl[lane];
        #pragma unroll
        for (int o = 16; o > 0; o >>= 1) {
            xq += __shfl_down_sync(0xffffffffu, xq, o);
            ld += __shfl_down_sync(0xffffffffu, ld, o);
        }
        if (lane == 0) out[0] = (float)(0.5 * (xq - ld));
    }
}

extern "C" void kernel_launch(void* const* d_in, const int* in_sizes, int n_in,
                              void* d_out, int out_size) {
    const float* x = (const float*)d_in[0];
    const float* w = (const float*)d_in[1];
    float* out = (float*)d_out;

    conv_kernel<<<dim3(8, 8, Bn), 256>>>(x, w);
    fused_stencil_kernel<<<dim3(8, 8, Bn * Tn), 256>>>(x);
    final_kernel<<<1, 1024>>>(out);
}